// round 15
// baseline (speedup 1.0000x reference)
#include <cuda_runtime.h>
#include <cuda_fp16.h>
#include <math.h>
#include <stdint.h>

// Problem constants
#define Bq 4
#define Sq 2048
#define Dm 1024
#define Hn 16
#define DHe 64
#define Mrows (Bq*Sq)   // 8192

// ---------------- scratch (__device__ globals; no allocs allowed) ----------
__device__ __half g_xh[(size_t)Mrows * Dm];
__device__ __half g_xl[(size_t)Mrows * Dm];
__device__ __half g_w [(size_t)4 * Dm * Dm];  // W^T single fp16, [n][k]
__device__ __half g_qh[(size_t)Mrows * Dm];   // [B,H,S,DH]
__device__ __half g_ql[(size_t)Mrows * Dm];
__device__ __half g_k [(size_t)Mrows * Dm];   // K single fp16
__device__ __half g_v [(size_t)Mrows * Dm];   // V single fp16
__device__ __half g_c [(size_t)Mrows * Dm];   // ctx single fp16, [B,S,D]

// ---------------- helpers ---------------------------------------------------
__device__ __forceinline__ uint32_t smem_u32(const void* p) {
    uint32_t a;
    asm("{ .reg .u64 t; cvta.to.shared.u64 t, %1; cvt.u32.u64 %0, t; }"
        : "=r"(a) : "l"(p));
    return a;
}
__device__ __forceinline__ void ldsm4(uint32_t* r, uint32_t a) {
    asm volatile("ldmatrix.sync.aligned.m8n8.x4.shared.b16 {%0,%1,%2,%3}, [%4];"
                 : "=r"(r[0]), "=r"(r[1]), "=r"(r[2]), "=r"(r[3]) : "r"(a));
}
__device__ __forceinline__ void ldsm4t(uint32_t* r, uint32_t a) {
    asm volatile("ldmatrix.sync.aligned.m8n8.x4.trans.shared.b16 {%0,%1,%2,%3}, [%4];"
                 : "=r"(r[0]), "=r"(r[1]), "=r"(r[2]), "=r"(r[3]) : "r"(a));
}
__device__ __forceinline__ void mma16816h(float* d, const uint32_t* a,
                                          uint32_t b0, uint32_t b1) {
    asm volatile(
        "mma.sync.aligned.m16n8k16.row.col.f32.f16.f16.f32 "
        "{%0,%1,%2,%3},{%4,%5,%6,%7},{%8,%9},{%0,%1,%2,%3};"
        : "+f"(d[0]), "+f"(d[1]), "+f"(d[2]), "+f"(d[3])
        : "r"(a[0]), "r"(a[1]), "r"(a[2]), "r"(a[3]), "r"(b0), "r"(b1));
}
#define CP_ASYNC16(dst, src) \
    asm volatile("cp.async.cg.shared.global [%0], [%1], 16;" :: "r"(dst), "l"(src) : "memory")
#define CP_COMMIT() asm volatile("cp.async.commit_group;" ::: "memory")
#define CP_WAIT(N)  asm volatile("cp.async.wait_group %0;" :: "n"(N) : "memory")

// fp16 pack / 2-term split of a float pair
__device__ __forceinline__ uint32_t packh2(float a, float b) {
    __half2 h = __floats2half2_rn(a, b);
    return *(uint32_t*)&h;
}
__device__ __forceinline__ void split2h(float a, float b, uint32_t& hp, uint32_t& lp) {
    __half2 h = __floats2half2_rn(a, b);
    float2 hf = __half22float2(h);
    __half2 l = __floats2half2_rn(a - hf.x, b - hf.y);
    hp = *(uint32_t*)&h;
    lp = *(uint32_t*)&l;
}

// ---------------- split kernels --------------------------------------------
__global__ void fsplit_kernel(const float* __restrict__ X,
                              __half* __restrict__ H, __half* __restrict__ L, int n4)
{
    const int stride = gridDim.x * blockDim.x;
    for (int i = blockIdx.x * blockDim.x + threadIdx.x; i < n4; i += 2 * stride) {
        float4 v0 = ((const float4*)X)[i];
        const int i2 = i + stride;
        float4 v1 = (i2 < n4) ? ((const float4*)X)[i2] : make_float4(0, 0, 0, 0);
        uint32_t h01, l01, h23, l23;
        split2h(v0.x, v0.y, h01, l01);
        split2h(v0.z, v0.w, h23, l23);
        ((uint2*)H)[i] = make_uint2(h01, h23);
        ((uint2*)L)[i] = make_uint2(l01, l23);
        if (i2 < n4) {
            split2h(v1.x, v1.y, h01, l01);
            split2h(v1.z, v1.w, h23, l23);
            ((uint2*)H)[i2] = make_uint2(h01, h23);
            ((uint2*)L)[i2] = make_uint2(l01, l23);
        }
    }
}

// transpose + single fp16 round, all 4 weights (z selects)
__global__ void wsplit_kernel(const float* __restrict__ W0, const float* __restrict__ W1,
                              const float* __restrict__ W2, const float* __restrict__ W3,
                              __half* __restrict__ TA)
{
    __shared__ float t[32][33];
    const int z = blockIdx.z;
    const float* W = (z == 0) ? W0 : (z == 1) ? W1 : (z == 2) ? W2 : W3;
    __half* T = TA + (size_t)z * Dm * Dm;
    const int bx = blockIdx.x * 32;
    const int by = blockIdx.y * 32;
    const int row = threadIdx.x >> 5;
    const int col = threadIdx.x & 31;
#pragma unroll
    for (int p = 0; p < 4; p++)
        t[row + 8 * p][col] = W[(size_t)(by + row + 8 * p) * Dm + bx + col];
    __syncthreads();
#pragma unroll
    for (int p = 0; p < 4; p++) {
        const int n = bx + row + 8 * p;
        const int k = by + col;
        T[(size_t)n * Dm + k] = __float2half_rn(t[col][row + 8 * p]);
    }
}

// ---------------- HMMA GEMM core --------------------------------------------
// 128x128 CTA tile, 128 threads, 4 warps of 64x64. BK=32, 2-stage cp.async.
// TWO=true: A split (Ah,Al), 2 MMAs; TWO=false: A single (Ah), 1 MMA.
constexpr int APAD    = 40;
constexpr int TILE_B  = 128 * APAD * 2;        // 10240
constexpr int STAGE_B = 3 * TILE_B;            // 30720 (Ah, Al, B)
constexpr int SMEM_GEMM = 2 * STAGE_B;         // 61440
constexpr int NST = Dm / 32;                   // 32

template <bool TWO>
__device__ __forceinline__ void g_load_stage(
    int s, int tid, uint32_t sb,
    const __half* Ah, const __half* Al, const __half* B, int m0, int n0)
{
    const int k0 = s * 32;
    const uint32_t base = sb + (s & 1) * STAGE_B;
#pragma unroll
    for (int i = 0; i < 12; i++) {
        const int id = tid + i * 128;
        const int tile = id >> 9;           // 0:Ah 1:Al 2:B
        if (!TWO && tile == 1) continue;    // skip Al traffic in 1-term mode
        const int idx = id & 511;
        const int row = idx >> 2;
        const int ch  = idx & 3;
        const int gk  = k0 + ch * 8;
        const __half* src;
        if (tile == 0)      src = Ah + (size_t)(m0 + row) * Dm + gk;
        else if (tile == 1) src = Al + (size_t)(m0 + row) * Dm + gk;
        else                src = B  + (size_t)(n0 + row) * Dm + gk;
        const uint32_t dst = base + tile * TILE_B + row * (APAD * 2) + ch * 16;
        CP_ASYNC16(dst, src);
    }
    CP_COMMIT();
}

template <bool TWO>
__device__ __forceinline__ void gemm_core(
    uint32_t sb, int tid, int wid, int lane,
    const __half* Ah, const __half* Al, const __half* B,
    int m0, int n0, float acc[4][8][4])
{
    const int warp_m = wid & 1;
    const int warp_n = wid >> 1;
    const int a_r = (lane & 7) + ((lane >> 3) & 1) * 8;
    const int a_c = ((lane >> 4) & 1) * 8;
    const uint32_t a_off = (uint32_t)((warp_m * 64 + a_r) * APAD + a_c) * 2;
    const int b_n = (lane & 7) + ((lane >> 4) & 1) * 8;
    const int b_k = ((lane >> 3) & 1) * 8;
    const uint32_t b_off = (uint32_t)((warp_n * 64 + b_n) * APAD + b_k) * 2;

#pragma unroll
    for (int i = 0; i < 4; i++)
#pragma unroll
        for (int j = 0; j < 8; j++)
#pragma unroll
            for (int e = 0; e < 4; e++) acc[i][j][e] = 0.f;

    g_load_stage<TWO>(0, tid, sb, Ah, Al, B, m0, n0);
    g_load_stage<TWO>(1, tid, sb, Ah, Al, B, m0, n0);

    for (int s = 0; s < NST; s++) {
        if (s + 2 < NST) CP_WAIT(1); else CP_WAIT(0);
        __syncthreads();
        const uint32_t base = sb + (s & 1) * STAGE_B;
#pragma unroll
        for (int ks = 0; ks < 2; ks++) {
            const uint32_t kb = ks * 32;
            uint32_t ah[4][4], al[4][4], bb[4][4];
#pragma unroll
            for (int mf = 0; mf < 4; mf++) {
                const uint32_t ro = mf * 16 * APAD * 2 + kb;
                ldsm4(ah[mf], base + 0 * TILE_B + a_off + ro);
                if (TWO) ldsm4(al[mf], base + 1 * TILE_B + a_off + ro);
            }
#pragma unroll
            for (int nh = 0; nh < 4; nh++) {
                const uint32_t ro = nh * 16 * APAD * 2 + kb;
                ldsm4(bb[nh], base + 2 * TILE_B + b_off + ro);
            }
#pragma unroll
            for (int mf = 0; mf < 4; mf++) {
#pragma unroll
                for (int nf = 0; nf < 8; nf++) {
                    const int nh = nf >> 1;
                    const int sel = (nf & 1) * 2;
                    const uint32_t b0 = bb[nh][sel], b1 = bb[nh][sel + 1];
                    mma16816h(acc[mf][nf], ah[mf], b0, b1);
                    if (TWO) mma16816h(acc[mf][nf], al[mf], b0, b1);
                }
            }
        }
        __syncthreads();
        if (s + 2 < NST)
            g_load_stage<TWO>(s + 2, tid, sb, Ah, Al, B, m0, n0);
    }
}

// fused Q/K/V projection: Q = 2-term split output pair, K/V = 1-term single
__global__ __launch_bounds__(128)
void gemm_qkv(const __half* __restrict__ Ah, const __half* __restrict__ Al,
              const __half* __restrict__ WA,
              __half* __restrict__ Qh, __half* __restrict__ Ql,
              __half* __restrict__ Ks, __half* __restrict__ Vs)
{
    extern __shared__ char smem[];
    const uint32_t sb = smem_u32(smem);
    const int tid = threadIdx.x, wid = tid >> 5, lane = tid & 31;
    const int m0 = blockIdx.y * 128;
    const int ng = blockIdx.x * 128;
    const int widx = ng >> 10;
    const int n0 = ng & 1023;
    const __half* B = WA + (size_t)widx * Dm * Dm;

    float acc[4][8][4];
    if (widx == 0) gemm_core<true >(sb, tid, wid, lane, Ah, Al, B, m0, n0, acc);
    else           gemm_core<false>(sb, tid, wid, lane, Ah, Al, B, m0, n0, acc);

    const int warp_m = wid & 1, warp_n = wid >> 1;
    const int g = lane >> 2, q = lane & 3;
#pragma unroll
    for (int mf = 0; mf < 4; mf++)
#pragma unroll
        for (int nf = 0; nf < 8; nf++)
#pragma unroll
            for (int hrow = 0; hrow < 2; hrow++) {
                const int m = m0 + warp_m * 64 + mf * 16 + g + hrow * 8;
                const int n = n0 + warp_n * 64 + nf * 8 + q * 2;
                const int bb = m >> 11, ss = m & (Sq - 1);
                const int h2 = n >> 6, dh = n & 63;
                const size_t off = ((size_t)((bb * Hn + h2) * Sq + ss)) * DHe + dh;
                const float v0 = acc[mf][nf][hrow * 2 + 0];
                const float v1 = acc[mf][nf][hrow * 2 + 1];
                if (widx == 0) {
                    uint32_t hp, lp;
                    split2h(v0, v1, hp, lp);
                    *(uint32_t*)(Qh + off) = hp;
                    *(uint32_t*)(Ql + off) = lp;
                } else {
                    __half* dst = (widx == 1) ? Ks : Vs;
                    *(uint32_t*)(dst + off) = packh2(v0, v1);
                }
            }
}

// O projection: single-term A (ctx fp16), fp32 output
__global__ __launch_bounds__(128)
void gemm_out(const __half* __restrict__ A, const __half* __restrict__ B,
              float* __restrict__ Cf)
{
    extern __shared__ char smem[];
    const uint32_t sb = smem_u32(smem);
    const int tid = threadIdx.x, wid = tid >> 5, lane = tid & 31;
    const int m0 = blockIdx.y * 128;
    const int n0 = blockIdx.x * 128;

    float acc[4][8][4];
    gemm_core<false>(sb, tid, wid, lane, A, A, B, m0, n0, acc);

    const int warp_m = wid & 1, warp_n = wid >> 1;
    const int g = lane >> 2, q = lane & 3;
#pragma unroll
    for (int mf = 0; mf < 4; mf++)
#pragma unroll
        for (int nf = 0; nf < 8; nf++)
#pragma unroll
            for (int hrow = 0; hrow < 2; hrow++) {
                const int m = m0 + warp_m * 64 + mf * 16 + g + hrow * 8;
                const int n = n0 + warp_n * 64 + nf * 8 + q * 2;
                *(float2*)(Cf + (size_t)m * Dm + n) =
                    make_float2(acc[mf][nf][hrow * 2 + 0], acc[mf][nf][hrow * 2 + 1]);
            }
}

// ---------------- tensor-core causal flash attention ------------------------
// 256 threads, 8 warps x 16 q-rows = 128 q-rows/block, KV tiles of 64.
// Q split fp16 (2 arrays), K/V single fp16; ctx written single fp16.
constexpr int ASTB = 144;
constexpr int Q_ARR     = 128 * ASTB;            // 18432 per Q array
constexpr int KV_ARR    = 64 * ASTB;             // 9216
constexpr int STAGE_ATT = 2 * KV_ARR;            // 18432 (K, V)
constexpr int SMEM_ATT  = 2 * Q_ARR + STAGE_ATT; // 55296

__device__ __forceinline__ void att_load_kv(
    uint32_t dstbase, int tid,
    const __half* K, const __half* V, size_t off)
{
#pragma unroll
    for (int i = 0; i < 4; i++) {
        const int id = tid + i * 256;
        const int arr = id >> 9;             // 0:K 1:V
        const int idx = id & 511;
        const int row = idx >> 3;
        const int ch  = idx & 7;
        const __half* p = arr ? V : K;
        CP_ASYNC16(dstbase + arr * KV_ARR + row * ASTB + ch * 16,
                   p + off + (size_t)row * DHe + ch * 8);
    }
    CP_COMMIT();
}

__global__ __launch_bounds__(256, 2)
void attn_tc(const __half* __restrict__ Qh, const __half* __restrict__ Ql,
             const __half* __restrict__ K, const __half* __restrict__ V,
             __half* __restrict__ C)
{
    extern __shared__ char smem[];
    const uint32_t sb = smem_u32(smem);          // Q area; first 18KB reused as stage1
    const uint32_t sbB = sb + 2 * Q_ARR;         // stage0
    const int tid  = threadIdx.x;
    const int w    = tid >> 5;
    const int lane = tid & 31;
    const int qt   = (int)gridDim.x - 1 - (int)blockIdx.x;   // heavy first
    const int bhid = blockIdx.y;
    const int b = bhid >> 4, h = bhid & 15;
    const size_t bhoff = (size_t)bhid * Sq * DHe;

    // ---- load Q tile (hi at sb, lo at sb+Q_ARR): 2048 16B chunks ----
#pragma unroll
    for (int i = 0; i < 8; i++) {
        const int id  = tid + i * 256;           // 0..2047
        const int arr = id >> 10;                // 0:hi 1:lo
        const int idx = id & 1023;
        const int row = idx >> 3, ch = idx & 7;
        const __half* src = (arr ? Ql : Qh) + bhoff + (size_t)(qt * 128 + row) * DHe + ch * 8;
        CP_ASYNC16(sb + arr * Q_ARR + row * ASTB + ch * 16, src);
    }
    CP_COMMIT();

    att_load_kv(sbB, tid, K, V, bhoff);          // kv tile 0 -> stage0

    CP_WAIT(1);                                  // Q ready
    __syncthreads();

    // ---- Q fragments ----
    const int a_r = (lane & 7) + ((lane >> 3) & 1) * 8;
    const int a_c = ((lane >> 4) & 1) * 8;
    const uint32_t a_off = (uint32_t)((16 * w + a_r) * ASTB + a_c * 2);
    uint32_t qa_h[4][4], qa_l[4][4];
#pragma unroll
    for (int t = 0; t < 4; t++) {
        ldsm4(qa_h[t], sb + a_off + t * 32);
        ldsm4(qa_l[t], sb + Q_ARR + a_off + t * 32);
    }
    __syncthreads();                             // Q area free for stage reuse

    const int b_n  = (lane & 7) + ((lane >> 4) & 1) * 8;
    const int b_k  = ((lane >> 3) & 1) * 8;
    const int v_kv = ((lane >> 3) & 1) * 8 + (lane & 7);
    const int v_d  = ((lane >> 4) & 1) * 8;
    const int g = lane >> 2;
    const int q = lane & 3;

    float acc_o[8][4];
#pragma unroll
    for (int i = 0; i < 8; i++)
#pragma unroll
        for (int e = 0; e < 4; e++) acc_o[i][e] = 0.f;
    float m0 = -INFINITY, m1 = -INFINITY, l0 = 0.f, l1 = 0.f;

    const int ntiles = 2 * qt + 2;
    const int rg0 = qt * 128 + 16 * w + g;
    const int rg1 = rg0 + 8;

    for (int kt = 0; kt < ntiles; kt++) {
        const int kv0 = kt * 64;
        if (kt + 1 < ntiles)
            att_load_kv(((kt + 1) & 1) ? sb : sbB, tid, K, V,
                        bhoff + (size_t)(kv0 + 64) * DHe);
        if (kt + 1 < ntiles) CP_WAIT(1); else CP_WAIT(0);
        __syncthreads();
        const uint32_t st = (kt & 1) ? sb : sbB;

        const bool active = (qt * 128 + 16 * w + 15) >= kv0;
        if (active) {
            // ---- scores: S = Q K^T (2-MMA: Qh.K + Ql.K) ----
            float sc[8][4];
#pragma unroll
            for (int i = 0; i < 8; i++)
#pragma unroll
                for (int e = 0; e < 4; e++) sc[i][e] = 0.f;

#pragma unroll
            for (int t = 0; t < 4; t++) {
                uint32_t kb[4][4];
#pragma unroll
                for (int g16 = 0; g16 < 4; g16++) {
                    const uint32_t off = (uint32_t)((16 * g16 + b_n) * ASTB + (t * 16 + b_k) * 2);
                    ldsm4(kb[g16], st + off);
                }
#pragma unroll
                for (int nf = 0; nf < 8; nf++) {
                    const int g16 = nf >> 1;
                    const int sel = (nf & 1) * 2;
                    mma16816h(sc[nf], qa_h[t], kb[g16][sel], kb[g16][sel + 1]);
                    mma16816h(sc[nf], qa_l[t], kb[g16][sel], kb[g16][sel + 1]);
                }
            }

#pragma unroll
            for (int nf = 0; nf < 8; nf++)
#pragma unroll
                for (int e = 0; e < 4; e++) sc[nf][e] *= 0.125f;

            if (kt >= 2 * qt) {
#pragma unroll
                for (int nf = 0; nf < 8; nf++) {
                    const int cg = kv0 + 8 * nf + 2 * q;
                    if (cg     > rg0) sc[nf][0] = -INFINITY;
                    if (cg + 1 > rg0) sc[nf][1] = -INFINITY;
                    if (cg     > rg1) sc[nf][2] = -INFINITY;
                    if (cg + 1 > rg1) sc[nf][3] = -INFINITY;
                }
            }

            float mx0 = -INFINITY, mx1 = -INFINITY;
#pragma unroll
            for (int nf = 0; nf < 8; nf++) {
                mx0 = fmaxf(mx0, fmaxf(sc[nf][0], sc[nf][1]));
                mx1 = fmaxf(mx1, fmaxf(sc[nf][2], sc[nf][3]));
            }
            mx0 = fmaxf(mx0, __shfl_xor_sync(0xffffffffu, mx0, 1));
            mx0 = fmaxf(mx0, __shfl_xor_sync(0xffffffffu, mx0, 2));
            mx1 = fmaxf(mx1, __shfl_xor_sync(0xffffffffu, mx1, 1));
            mx1 = fmaxf(mx1, __shfl_xor_sync(0xffffffffu, mx1, 2));

            const float mn0 = fmaxf(m0, mx0), mn1 = fmaxf(m1, mx1);
            const float al0 = __expf(m0 - mn0), al1 = __expf(m1 - mn1);

            float ps0 = 0.f, ps1 = 0.f;
#pragma unroll
            for (int nf = 0; nf < 8; nf++) {
                sc[nf][0] = __expf(sc[nf][0] - mn0);
                sc[nf][1] = __expf(sc[nf][1] - mn0);
                sc[nf][2] = __expf(sc[nf][2] - mn1);
                sc[nf][3] = __expf(sc[nf][3] - mn1);
                ps0 += sc[nf][0] + sc[nf][1];
                ps1 += sc[nf][2] + sc[nf][3];
            }
            ps0 += __shfl_xor_sync(0xffffffffu, ps0, 1);
            ps0 += __shfl_xor_sync(0xffffffffu, ps0, 2);
            ps1 += __shfl_xor_sync(0xffffffffu, ps1, 1);
            ps1 += __shfl_xor_sync(0xffffffffu, ps1, 2);

            l0 = l0 * al0 + ps0;
            l1 = l1 * al1 + ps1;
            m0 = mn0; m1 = mn1;
#pragma unroll
            for (int df = 0; df < 8; df++) {
                acc_o[df][0] *= al0; acc_o[df][1] *= al0;
                acc_o[df][2] *= al1; acc_o[df][3] *= al1;
            }

            // ---- pack P into split fp16 A-fragments ----
            uint32_t pa_h[4][4], pa_l[4][4];
#pragma unroll
            for (int t = 0; t < 4; t++) {
                split2h(sc[2 * t][0],     sc[2 * t][1],     pa_h[t][0], pa_l[t][0]);
                split2h(sc[2 * t][2],     sc[2 * t][3],     pa_h[t][1], pa_l[t][1]);
                split2h(sc[2 * t + 1][0], sc[2 * t + 1][1], pa_h[t][2], pa_l[t][2]);
                split2h(sc[2 * t + 1][2], sc[2 * t + 1][3], pa_h[t][3], pa_l[t][3]);
            }

            // ---- O += P V (2-MMA: Ph.V + Pl.V), V via ldmatrix.trans ----
#pragma unroll
            for (int t = 0; t < 4; t++) {
                uint32_t vb[4][4];
#pragma unroll
                for (int g16 = 0; g16 < 4; g16++) {
                    const uint32_t off =
                        (uint32_t)((16 * t + v_kv) * ASTB + (16 * g16 + v_d) * 2);
                    ldsm4t(vb[g16], st + KV_ARR + off);
                }
#pragma unroll
                for (int df = 0; df < 8; df++) {
                    const int g16 = df >> 1;
                    const int sel = (df & 1) * 2;
                    mma16816h(acc_o[df], pa_h[t], vb[g16][sel], vb[g16][sel + 1]);
                    mma16816h(acc_o[df], pa_l[t], vb[g16][sel], vb[g16][sel + 1]);
                }
            }
        }
        __syncthreads();
    }

    // ---- epilogue: normalize, single fp16 round, write [B,S,D] ----
    const float i0 = 1.f / l0, i1 = 1.f / l1;
    const int s0 = qt * 128 + 16 * w + g;
    const size_t base0 = ((size_t)(b * Sq + s0)) * Dm + h * DHe;
    const size_t base1 = base0 + (size_t)8 * Dm;
#pragma unroll
    for (int df = 0; df < 8; df++) {
        const int d = 8 * df + 2 * q;
        *(uint32_t*)(C + base0 + d) = packh2(acc_o[df][0] * i0, acc_o[df][1] * i0);
        *(uint32_t*)(C + base1 + d) = packh2(acc_o[df][2] * i1, acc_o[df][3] * i1);
    }
}

// ---------------------------------------------------------------------------
extern "C" void kernel_launch(void* const* d_in, const int* in_sizes, int n_in,
                              void* d_out, int out_size)
{
    const float* x  = (const float*)d_in[0];
    const float* Wq = (const float*)d_in[1];
    const float* Wk = (const float*)d_in[2];
    const float* Wv = (const float*)d_in[3];
    const float* Wo = (const float*)d_in[4];
    float* out = (float*)d_out;

    __half *xh, *xl, *wp, *qh, *ql, *kp, *vp, *cp;
    cudaGetSymbolAddress((void**)&xh, g_xh);
    cudaGetSymbolAddress((void**)&xl, g_xl);
    cudaGetSymbolAddress((void**)&wp, g_w);
    cudaGetSymbolAddress((void**)&qh, g_qh);
    cudaGetSymbolAddress((void**)&ql, g_ql);
    cudaGetSymbolAddress((void**)&kp, g_k);
    cudaGetSymbolAddress((void**)&vp, g_v);
    cudaGetSymbolAddress((void**)&cp, g_c);

    cudaFuncSetAttribute(gemm_qkv, cudaFuncAttributeMaxDynamicSharedMemorySize, SMEM_GEMM);
    cudaFuncSetAttribute(gemm_out, cudaFuncAttributeMaxDynamicSharedMemorySize, SMEM_GEMM);
    cudaFuncSetAttribute(attn_tc,  cudaFuncAttributeMaxDynamicSharedMemorySize, SMEM_ATT);

    const int n4 = Mrows * Dm / 4;
    const size_t WSZ = (size_t)Dm * Dm;

    fsplit_kernel<<<2048, 256>>>(x, xh, xl, n4);
    wsplit_kernel<<<dim3(Dm / 32, Dm / 32, 4), 256>>>(Wq, Wk, Wv, Wo, wp);

    gemm_qkv<<<dim3(3 * Dm / 128, Mrows / 128), 128, SMEM_GEMM>>>(
        xh, xl, wp, qh, ql, kp, vp);

    attn_tc<<<dim3(Sq / 128, Bq * Hn), 256, SMEM_ATT>>>(qh, ql, kp, vp, cp);

    gemm_out<<<dim3(Dm / 128, Mrows / 128), 128, SMEM_GEMM>>>(
        cp, wp + 3 * WSZ, out);
}

// round 17
// speedup vs baseline: 1.4615x; 1.4615x over previous
#include <cuda_runtime.h>
#include <cuda_fp16.h>
#include <math.h>
#include <stdint.h>

// Problem constants
#define Bq 4
#define Sq 2048
#define Dm 1024
#define Hn 16
#define DHe 64
#define Mrows (Bq*Sq)   // 8192

// ---------------- scratch (__device__ globals; no allocs allowed) ----------
__device__ __half g_xh[(size_t)Mrows * Dm];
__device__ __half g_xl[(size_t)Mrows * Dm];
__device__ __half g_w [(size_t)4 * Dm * Dm];  // W^T single fp16, [n][k]
__device__ __half g_qh[(size_t)Mrows * Dm];   // [B,H,S,DH]
__device__ __half g_ql[(size_t)Mrows * Dm];
__device__ __half g_k [(size_t)Mrows * Dm];   // K single fp16
__device__ __half g_v [(size_t)Mrows * Dm];   // V single fp16
__device__ __half g_c [(size_t)Mrows * Dm];   // ctx single fp16, [B,S,D]

// ---------------- helpers ---------------------------------------------------
__device__ __forceinline__ uint32_t smem_u32(const void* p) {
    uint32_t a;
    asm("{ .reg .u64 t; cvta.to.shared.u64 t, %1; cvt.u32.u64 %0, t; }"
        : "=r"(a) : "l"(p));
    return a;
}
__device__ __forceinline__ void ldsm4(uint32_t* r, uint32_t a) {
    asm volatile("ldmatrix.sync.aligned.m8n8.x4.shared.b16 {%0,%1,%2,%3}, [%4];"
                 : "=r"(r[0]), "=r"(r[1]), "=r"(r[2]), "=r"(r[3]) : "r"(a));
}
__device__ __forceinline__ void ldsm4t(uint32_t* r, uint32_t a) {
    asm volatile("ldmatrix.sync.aligned.m8n8.x4.trans.shared.b16 {%0,%1,%2,%3}, [%4];"
                 : "=r"(r[0]), "=r"(r[1]), "=r"(r[2]), "=r"(r[3]) : "r"(a));
}
__device__ __forceinline__ void mma16816h(float* d, const uint32_t* a,
                                          uint32_t b0, uint32_t b1) {
    asm volatile(
        "mma.sync.aligned.m16n8k16.row.col.f32.f16.f16.f32 "
        "{%0,%1,%2,%3},{%4,%5,%6,%7},{%8,%9},{%0,%1,%2,%3};"
        : "+f"(d[0]), "+f"(d[1]), "+f"(d[2]), "+f"(d[3])
        : "r"(a[0]), "r"(a[1]), "r"(a[2]), "r"(a[3]), "r"(b0), "r"(b1));
}
#define CP_ASYNC16(dst, src) \
    asm volatile("cp.async.cg.shared.global [%0], [%1], 16;" :: "r"(dst), "l"(src) : "memory")
#define CP_COMMIT() asm volatile("cp.async.commit_group;" ::: "memory")
#define CP_WAIT(N)  asm volatile("cp.async.wait_group %0;" :: "n"(N) : "memory")

// fp16 pack / 2-term split of a float pair
__device__ __forceinline__ uint32_t packh2(float a, float b) {
    __half2 h = __floats2half2_rn(a, b);
    return *(uint32_t*)&h;
}
__device__ __forceinline__ void split2h(float a, float b, uint32_t& hp, uint32_t& lp) {
    __half2 h = __floats2half2_rn(a, b);
    float2 hf = __half22float2(h);
    __half2 l = __floats2half2_rn(a - hf.x, b - hf.y);
    hp = *(uint32_t*)&h;
    lp = *(uint32_t*)&l;
}

// ---------------- split kernels --------------------------------------------
__global__ void fsplit_kernel(const float* __restrict__ X,
                              __half* __restrict__ H, __half* __restrict__ L, int n4)
{
    const int stride = gridDim.x * blockDim.x;
    for (int i = blockIdx.x * blockDim.x + threadIdx.x; i < n4; i += 2 * stride) {
        float4 v0 = ((const float4*)X)[i];
        const int i2 = i + stride;
        float4 v1 = (i2 < n4) ? ((const float4*)X)[i2] : make_float4(0, 0, 0, 0);
        uint32_t h01, l01, h23, l23;
        split2h(v0.x, v0.y, h01, l01);
        split2h(v0.z, v0.w, h23, l23);
        ((uint2*)H)[i] = make_uint2(h01, h23);
        ((uint2*)L)[i] = make_uint2(l01, l23);
        if (i2 < n4) {
            split2h(v1.x, v1.y, h01, l01);
            split2h(v1.z, v1.w, h23, l23);
            ((uint2*)H)[i2] = make_uint2(h01, h23);
            ((uint2*)L)[i2] = make_uint2(l01, l23);
        }
    }
}

// transpose + single fp16 round, all 4 weights (z selects)
__global__ void wsplit_kernel(const float* __restrict__ W0, const float* __restrict__ W1,
                              const float* __restrict__ W2, const float* __restrict__ W3,
                              __half* __restrict__ TA)
{
    __shared__ float t[32][33];
    const int z = blockIdx.z;
    const float* W = (z == 0) ? W0 : (z == 1) ? W1 : (z == 2) ? W2 : W3;
    __half* T = TA + (size_t)z * Dm * Dm;
    const int bx = blockIdx.x * 32;
    const int by = blockIdx.y * 32;
    const int row = threadIdx.x >> 5;
    const int col = threadIdx.x & 31;
#pragma unroll
    for (int p = 0; p < 4; p++)
        t[row + 8 * p][col] = W[(size_t)(by + row + 8 * p) * Dm + bx + col];
    __syncthreads();
#pragma unroll
    for (int p = 0; p < 4; p++) {
        const int n = bx + row + 8 * p;
        const int k = by + col;
        T[(size_t)n * Dm + k] = __float2half_rn(t[col][row + 8 * p]);
    }
}

// ---------------- HMMA GEMM core --------------------------------------------
// 128x128 CTA tile, 128 threads, 4 warps of 64x64. BK=32, 2-stage cp.async.
// TWO=true: A split (Ah,Al), 2 MMAs; TWO=false: A single (Ah), 1 MMA.
constexpr int APAD    = 40;
constexpr int TILE_B  = 128 * APAD * 2;        // 10240
constexpr int STAGE_B = 3 * TILE_B;            // 30720 (Ah, Al, B)
constexpr int SMEM_GEMM = 2 * STAGE_B;         // 61440
constexpr int NST = Dm / 32;                   // 32

template <bool TWO>
__device__ __forceinline__ void g_load_stage(
    int s, int tid, uint32_t sb,
    const __half* Ah, const __half* Al, const __half* B, int m0, int n0)
{
    const int k0 = s * 32;
    const uint32_t base = sb + (s & 1) * STAGE_B;
#pragma unroll
    for (int i = 0; i < 12; i++) {
        const int id = tid + i * 128;
        const int tile = id >> 9;           // 0:Ah 1:Al 2:B
        if (!TWO && tile == 1) continue;    // skip Al traffic in 1-term mode
        const int idx = id & 511;
        const int row = idx >> 2;
        const int ch  = idx & 3;
        const int gk  = k0 + ch * 8;
        const __half* src;
        if (tile == 0)      src = Ah + (size_t)(m0 + row) * Dm + gk;
        else if (tile == 1) src = Al + (size_t)(m0 + row) * Dm + gk;
        else                src = B  + (size_t)(n0 + row) * Dm + gk;
        const uint32_t dst = base + tile * TILE_B + row * (APAD * 2) + ch * 16;
        CP_ASYNC16(dst, src);
    }
    CP_COMMIT();
}

template <bool TWO>
__device__ __forceinline__ void gemm_core(
    uint32_t sb, int tid, int wid, int lane,
    const __half* Ah, const __half* Al, const __half* B,
    int m0, int n0, float acc[4][8][4])
{
    const int warp_m = wid & 1;
    const int warp_n = wid >> 1;
    const int a_r = (lane & 7) + ((lane >> 3) & 1) * 8;
    const int a_c = ((lane >> 4) & 1) * 8;
    const uint32_t a_off = (uint32_t)((warp_m * 64 + a_r) * APAD + a_c) * 2;
    const int b_n = (lane & 7) + ((lane >> 4) & 1) * 8;
    const int b_k = ((lane >> 3) & 1) * 8;
    const uint32_t b_off = (uint32_t)((warp_n * 64 + b_n) * APAD + b_k) * 2;

#pragma unroll
    for (int i = 0; i < 4; i++)
#pragma unroll
        for (int j = 0; j < 8; j++)
#pragma unroll
            for (int e = 0; e < 4; e++) acc[i][j][e] = 0.f;

    g_load_stage<TWO>(0, tid, sb, Ah, Al, B, m0, n0);
    g_load_stage<TWO>(1, tid, sb, Ah, Al, B, m0, n0);

    for (int s = 0; s < NST; s++) {
        if (s + 2 < NST) CP_WAIT(1); else CP_WAIT(0);
        __syncthreads();
        const uint32_t base = sb + (s & 1) * STAGE_B;
#pragma unroll
        for (int ks = 0; ks < 2; ks++) {
            const uint32_t kb = ks * 32;
            uint32_t ah[4][4], al[4][4], bb[4][4];
#pragma unroll
            for (int mf = 0; mf < 4; mf++) {
                const uint32_t ro = mf * 16 * APAD * 2 + kb;
                ldsm4(ah[mf], base + 0 * TILE_B + a_off + ro);
                if (TWO) ldsm4(al[mf], base + 1 * TILE_B + a_off + ro);
            }
#pragma unroll
            for (int nh = 0; nh < 4; nh++) {
                const uint32_t ro = nh * 16 * APAD * 2 + kb;
                ldsm4(bb[nh], base + 2 * TILE_B + b_off + ro);
            }
#pragma unroll
            for (int mf = 0; mf < 4; mf++) {
#pragma unroll
                for (int nf = 0; nf < 8; nf++) {
                    const int nh = nf >> 1;
                    const int sel = (nf & 1) * 2;
                    const uint32_t b0 = bb[nh][sel], b1 = bb[nh][sel + 1];
                    mma16816h(acc[mf][nf], ah[mf], b0, b1);
                    if (TWO) mma16816h(acc[mf][nf], al[mf], b0, b1);
                }
            }
        }
        __syncthreads();
        if (s + 2 < NST)
            g_load_stage<TWO>(s + 2, tid, sb, Ah, Al, B, m0, n0);
    }
}

// Q projection: 2-term split A, split output pair, [B,H,S,DH]
__global__ __launch_bounds__(128)
void gemm_q(const __half* __restrict__ Ah, const __half* __restrict__ Al,
            const __half* __restrict__ Wq,
            __half* __restrict__ Qh, __half* __restrict__ Ql)
{
    extern __shared__ char smem[];
    const uint32_t sb = smem_u32(smem);
    const int tid = threadIdx.x, wid = tid >> 5, lane = tid & 31;
    const int m0 = blockIdx.y * 128;
    const int n0 = blockIdx.x * 128;

    float acc[4][8][4];
    gemm_core<true>(sb, tid, wid, lane, Ah, Al, Wq, m0, n0, acc);

    const int warp_m = wid & 1, warp_n = wid >> 1;
    const int g = lane >> 2, q = lane & 3;
#pragma unroll
    for (int mf = 0; mf < 4; mf++)
#pragma unroll
        for (int nf = 0; nf < 8; nf++)
#pragma unroll
            for (int hrow = 0; hrow < 2; hrow++) {
                const int m = m0 + warp_m * 64 + mf * 16 + g + hrow * 8;
                const int n = n0 + warp_n * 64 + nf * 8 + q * 2;
                const int bb = m >> 11, ss = m & (Sq - 1);
                const int h2 = n >> 6, dh = n & 63;
                const size_t off = ((size_t)((bb * Hn + h2) * Sq + ss)) * DHe + dh;
                uint32_t hp, lp;
                split2h(acc[mf][nf][hrow * 2 + 0], acc[mf][nf][hrow * 2 + 1], hp, lp);
                *(uint32_t*)(Qh + off) = hp;
                *(uint32_t*)(Ql + off) = lp;
            }
}

// K/V projection: 1-term A, single fp16 output, [B,H,S,DH]; grid.x covers 2048
__global__ __launch_bounds__(128)
void gemm_kv(const __half* __restrict__ Ah, const __half* __restrict__ WA,
             __half* __restrict__ Ks, __half* __restrict__ Vs)
{
    extern __shared__ char smem[];
    const uint32_t sb = smem_u32(smem);
    const int tid = threadIdx.x, wid = tid >> 5, lane = tid & 31;
    const int m0 = blockIdx.y * 128;
    const int ng = blockIdx.x * 128;          // 0..2047
    const int widx = ng >> 10;                // 0:K 1:V
    const int n0 = ng & 1023;
    const __half* B = WA + (size_t)widx * Dm * Dm;
    __half* dst = widx ? Vs : Ks;

    float acc[4][8][4];
    gemm_core<false>(sb, tid, wid, lane, Ah, Ah, B, m0, n0, acc);

    const int warp_m = wid & 1, warp_n = wid >> 1;
    const int g = lane >> 2, q = lane & 3;
#pragma unroll
    for (int mf = 0; mf < 4; mf++)
#pragma unroll
        for (int nf = 0; nf < 8; nf++)
#pragma unroll
            for (int hrow = 0; hrow < 2; hrow++) {
                const int m = m0 + warp_m * 64 + mf * 16 + g + hrow * 8;
                const int n = n0 + warp_n * 64 + nf * 8 + q * 2;
                const int bb = m >> 11, ss = m & (Sq - 1);
                const int h2 = n >> 6, dh = n & 63;
                const size_t off = ((size_t)((bb * Hn + h2) * Sq + ss)) * DHe + dh;
                *(uint32_t*)(dst + off) =
                    packh2(acc[mf][nf][hrow * 2 + 0], acc[mf][nf][hrow * 2 + 1]);
            }
}

// O projection: single-term A (ctx fp16), fp32 output
__global__ __launch_bounds__(128)
void gemm_out(const __half* __restrict__ A, const __half* __restrict__ B,
              float* __restrict__ Cf)
{
    extern __shared__ char smem[];
    const uint32_t sb = smem_u32(smem);
    const int tid = threadIdx.x, wid = tid >> 5, lane = tid & 31;
    const int m0 = blockIdx.y * 128;
    const int n0 = blockIdx.x * 128;

    float acc[4][8][4];
    gemm_core<false>(sb, tid, wid, lane, A, A, B, m0, n0, acc);

    const int warp_m = wid & 1, warp_n = wid >> 1;
    const int g = lane >> 2, q = lane & 3;
#pragma unroll
    for (int mf = 0; mf < 4; mf++)
#pragma unroll
        for (int nf = 0; nf < 8; nf++)
#pragma unroll
            for (int hrow = 0; hrow < 2; hrow++) {
                const int m = m0 + warp_m * 64 + mf * 16 + g + hrow * 8;
                const int n = n0 + warp_n * 64 + nf * 8 + q * 2;
                *(float2*)(Cf + (size_t)m * Dm + n) =
                    make_float2(acc[mf][nf][hrow * 2 + 0], acc[mf][nf][hrow * 2 + 1]);
            }
}

// ---------------- tensor-core causal flash attention ------------------------
// 256 threads, 8 warps x 16 q-rows = 128 q-rows/block, KV tiles of 64.
// Q split fp16 (2 arrays), K/V single fp16; ctx written single fp16.
constexpr int ASTB = 144;
constexpr int Q_ARR     = 128 * ASTB;            // 18432 per Q array
constexpr int KV_ARR    = 64 * ASTB;             // 9216
constexpr int STAGE_ATT = 2 * KV_ARR;            // 18432 (K, V)
constexpr int SMEM_ATT  = 2 * Q_ARR + STAGE_ATT; // 55296

__device__ __forceinline__ void att_load_kv(
    uint32_t dstbase, int tid,
    const __half* K, const __half* V, size_t off)
{
#pragma unroll
    for (int i = 0; i < 4; i++) {
        const int id = tid + i * 256;
        const int arr = id >> 9;             // 0:K 1:V
        const int idx = id & 511;
        const int row = idx >> 3;
        const int ch  = idx & 7;
        const __half* p = arr ? V : K;
        CP_ASYNC16(dstbase + arr * KV_ARR + row * ASTB + ch * 16,
                   p + off + (size_t)row * DHe + ch * 8);
    }
    CP_COMMIT();
}

__global__ __launch_bounds__(256, 2)
void attn_tc(const __half* __restrict__ Qh, const __half* __restrict__ Ql,
             const __half* __restrict__ K, const __half* __restrict__ V,
             __half* __restrict__ C)
{
    extern __shared__ char smem[];
    const uint32_t sb = smem_u32(smem);          // Q area; first 18KB reused as stage1
    const uint32_t sbB = sb + 2 * Q_ARR;         // stage0
    const int tid  = threadIdx.x;
    const int w    = tid >> 5;
    const int lane = tid & 31;
    const int qt   = (int)gridDim.x - 1 - (int)blockIdx.x;   // heavy first
    const int bhid = blockIdx.y;
    const int b = bhid >> 4, h = bhid & 15;
    const size_t bhoff = (size_t)bhid * Sq * DHe;

    // ---- load Q tile (hi at sb, lo at sb+Q_ARR): 2048 16B chunks ----
#pragma unroll
    for (int i = 0; i < 8; i++) {
        const int id  = tid + i * 256;           // 0..2047
        const int arr = id >> 10;                // 0:hi 1:lo
        const int idx = id & 1023;
        const int row = idx >> 3, ch = idx & 7;
        const __half* src = (arr ? Ql : Qh) + bhoff + (size_t)(qt * 128 + row) * DHe + ch * 8;
        CP_ASYNC16(sb + arr * Q_ARR + row * ASTB + ch * 16, src);
    }
    CP_COMMIT();

    att_load_kv(sbB, tid, K, V, bhoff);          // kv tile 0 -> stage0

    CP_WAIT(1);                                  // Q ready
    __syncthreads();

    // ---- Q fragments ----
    const int a_r = (lane & 7) + ((lane >> 3) & 1) * 8;
    const int a_c = ((lane >> 4) & 1) * 8;
    const uint32_t a_off = (uint32_t)((16 * w + a_r) * ASTB + a_c * 2);
    uint32_t qa_h[4][4], qa_l[4][4];
#pragma unroll
    for (int t = 0; t < 4; t++) {
        ldsm4(qa_h[t], sb + a_off + t * 32);
        ldsm4(qa_l[t], sb + Q_ARR + a_off + t * 32);
    }
    __syncthreads();                             // Q area free for stage reuse

    const int b_n  = (lane & 7) + ((lane >> 4) & 1) * 8;
    const int b_k  = ((lane >> 3) & 1) * 8;
    const int v_kv = ((lane >> 3) & 1) * 8 + (lane & 7);
    const int v_d  = ((lane >> 4) & 1) * 8;
    const int g = lane >> 2;
    const int q = lane & 3;

    float acc_o[8][4];
#pragma unroll
    for (int i = 0; i < 8; i++)
#pragma unroll
        for (int e = 0; e < 4; e++) acc_o[i][e] = 0.f;
    float m0 = -INFINITY, m1 = -INFINITY, l0 = 0.f, l1 = 0.f;

    const int ntiles = 2 * qt + 2;
    const int rg0 = qt * 128 + 16 * w + g;
    const int rg1 = rg0 + 8;

    for (int kt = 0; kt < ntiles; kt++) {
        const int kv0 = kt * 64;
        if (kt + 1 < ntiles)
            att_load_kv(((kt + 1) & 1) ? sb : sbB, tid, K, V,
                        bhoff + (size_t)(kv0 + 64) * DHe);
        if (kt + 1 < ntiles) CP_WAIT(1); else CP_WAIT(0);
        __syncthreads();
        const uint32_t st = (kt & 1) ? sb : sbB;

        const bool active = (qt * 128 + 16 * w + 15) >= kv0;
        if (active) {
            // ---- scores: S = Q K^T (2-MMA: Qh.K + Ql.K) ----
            float sc[8][4];
#pragma unroll
            for (int i = 0; i < 8; i++)
#pragma unroll
                for (int e = 0; e < 4; e++) sc[i][e] = 0.f;

#pragma unroll
            for (int t = 0; t < 4; t++) {
                uint32_t kb[4][4];
#pragma unroll
                for (int g16 = 0; g16 < 4; g16++) {
                    const uint32_t off = (uint32_t)((16 * g16 + b_n) * ASTB + (t * 16 + b_k) * 2);
                    ldsm4(kb[g16], st + off);
                }
#pragma unroll
                for (int nf = 0; nf < 8; nf++) {
                    const int g16 = nf >> 1;
                    const int sel = (nf & 1) * 2;
                    mma16816h(sc[nf], qa_h[t], kb[g16][sel], kb[g16][sel + 1]);
                    mma16816h(sc[nf], qa_l[t], kb[g16][sel], kb[g16][sel + 1]);
                }
            }

#pragma unroll
            for (int nf = 0; nf < 8; nf++)
#pragma unroll
                for (int e = 0; e < 4; e++) sc[nf][e] *= 0.125f;

            if (kt >= 2 * qt) {
#pragma unroll
                for (int nf = 0; nf < 8; nf++) {
                    const int cg = kv0 + 8 * nf + 2 * q;
                    if (cg     > rg0) sc[nf][0] = -INFINITY;
                    if (cg + 1 > rg0) sc[nf][1] = -INFINITY;
                    if (cg     > rg1) sc[nf][2] = -INFINITY;
                    if (cg + 1 > rg1) sc[nf][3] = -INFINITY;
                }
            }

            float mx0 = -INFINITY, mx1 = -INFINITY;
#pragma unroll
            for (int nf = 0; nf < 8; nf++) {
                mx0 = fmaxf(mx0, fmaxf(sc[nf][0], sc[nf][1]));
                mx1 = fmaxf(mx1, fmaxf(sc[nf][2], sc[nf][3]));
            }
            mx0 = fmaxf(mx0, __shfl_xor_sync(0xffffffffu, mx0, 1));
            mx0 = fmaxf(mx0, __shfl_xor_sync(0xffffffffu, mx0, 2));
            mx1 = fmaxf(mx1, __shfl_xor_sync(0xffffffffu, mx1, 1));
            mx1 = fmaxf(mx1, __shfl_xor_sync(0xffffffffu, mx1, 2));

            const float mn0 = fmaxf(m0, mx0), mn1 = fmaxf(m1, mx1);
            const float al0 = __expf(m0 - mn0), al1 = __expf(m1 - mn1);

            float ps0 = 0.f, ps1 = 0.f;
#pragma unroll
            for (int nf = 0; nf < 8; nf++) {
                sc[nf][0] = __expf(sc[nf][0] - mn0);
                sc[nf][1] = __expf(sc[nf][1] - mn0);
                sc[nf][2] = __expf(sc[nf][2] - mn1);
                sc[nf][3] = __expf(sc[nf][3] - mn1);
                ps0 += sc[nf][0] + sc[nf][1];
                ps1 += sc[nf][2] + sc[nf][3];
            }
            ps0 += __shfl_xor_sync(0xffffffffu, ps0, 1);
            ps0 += __shfl_xor_sync(0xffffffffu, ps0, 2);
            ps1 += __shfl_xor_sync(0xffffffffu, ps1, 1);
            ps1 += __shfl_xor_sync(0xffffffffu, ps1, 2);

            l0 = l0 * al0 + ps0;
            l1 = l1 * al1 + ps1;
            m0 = mn0; m1 = mn1;
#pragma unroll
            for (int df = 0; df < 8; df++) {
                acc_o[df][0] *= al0; acc_o[df][1] *= al0;
                acc_o[df][2] *= al1; acc_o[df][3] *= al1;
            }

            // ---- pack P into split fp16 A-fragments ----
            uint32_t pa_h[4][4], pa_l[4][4];
#pragma unroll
            for (int t = 0; t < 4; t++) {
                split2h(sc[2 * t][0],     sc[2 * t][1],     pa_h[t][0], pa_l[t][0]);
                split2h(sc[2 * t][2],     sc[2 * t][3],     pa_h[t][1], pa_l[t][1]);
                split2h(sc[2 * t + 1][0], sc[2 * t + 1][1], pa_h[t][2], pa_l[t][2]);
                split2h(sc[2 * t + 1][2], sc[2 * t + 1][3], pa_h[t][3], pa_l[t][3]);
            }

            // ---- O += P V (2-MMA: Ph.V + Pl.V), V via ldmatrix.trans ----
#pragma unroll
            for (int t = 0; t < 4; t++) {
                uint32_t vb[4][4];
#pragma unroll
                for (int g16 = 0; g16 < 4; g16++) {
                    const uint32_t off =
                        (uint32_t)((16 * t + v_kv) * ASTB + (16 * g16 + v_d) * 2);
                    ldsm4t(vb[g16], st + KV_ARR + off);
                }
#pragma unroll
                for (int df = 0; df < 8; df++) {
                    const int g16 = df >> 1;
                    const int sel = (df & 1) * 2;
                    mma16816h(acc_o[df], pa_h[t], vb[g16][sel], vb[g16][sel + 1]);
                    mma16816h(acc_o[df], pa_l[t], vb[g16][sel], vb[g16][sel + 1]);
                }
            }
        }
        __syncthreads();
    }

    // ---- epilogue: normalize, single fp16 round, write [B,S,D] ----
    const float i0 = 1.f / l0, i1 = 1.f / l1;
    const int s0 = qt * 128 + 16 * w + g;
    const size_t base0 = ((size_t)(b * Sq + s0)) * Dm + h * DHe;
    const size_t base1 = base0 + (size_t)8 * Dm;
#pragma unroll
    for (int df = 0; df < 8; df++) {
        const int d = 8 * df + 2 * q;
        *(uint32_t*)(C + base0 + d) = packh2(acc_o[df][0] * i0, acc_o[df][1] * i0);
        *(uint32_t*)(C + base1 + d) = packh2(acc_o[df][2] * i1, acc_o[df][3] * i1);
    }
}

// ---------------------------------------------------------------------------
extern "C" void kernel_launch(void* const* d_in, const int* in_sizes, int n_in,
                              void* d_out, int out_size)
{
    const float* x  = (const float*)d_in[0];
    const float* Wq = (const float*)d_in[1];
    const float* Wk = (const float*)d_in[2];
    const float* Wv = (const float*)d_in[3];
    const float* Wo = (const float*)d_in[4];
    float* out = (float*)d_out;

    __half *xh, *xl, *wp, *qh, *ql, *kp, *vp, *cp;
    cudaGetSymbolAddress((void**)&xh, g_xh);
    cudaGetSymbolAddress((void**)&xl, g_xl);
    cudaGetSymbolAddress((void**)&wp, g_w);
    cudaGetSymbolAddress((void**)&qh, g_qh);
    cudaGetSymbolAddress((void**)&ql, g_ql);
    cudaGetSymbolAddress((void**)&kp, g_k);
    cudaGetSymbolAddress((void**)&vp, g_v);
    cudaGetSymbolAddress((void**)&cp, g_c);

    cudaFuncSetAttribute(gemm_q,   cudaFuncAttributeMaxDynamicSharedMemorySize, SMEM_GEMM);
    cudaFuncSetAttribute(gemm_kv,  cudaFuncAttributeMaxDynamicSharedMemorySize, SMEM_GEMM);
    cudaFuncSetAttribute(gemm_out, cudaFuncAttributeMaxDynamicSharedMemorySize, SMEM_GEMM);
    cudaFuncSetAttribute(attn_tc,  cudaFuncAttributeMaxDynamicSharedMemorySize, SMEM_ATT);

    const int n4 = Mrows * Dm / 4;
    const size_t WSZ = (size_t)Dm * Dm;

    fsplit_kernel<<<2048, 256>>>(x, xh, xl, n4);
    wsplit_kernel<<<dim3(Dm / 32, Dm / 32, 4), 256>>>(Wq, Wk, Wv, Wo, wp);

    gemm_q <<<dim3(Dm / 128, Mrows / 128), 128, SMEM_GEMM>>>(xh, xl, wp + 0 * WSZ, qh, ql);
    gemm_kv<<<dim3(2 * Dm / 128, Mrows / 128), 128, SMEM_GEMM>>>(xh, wp + 1 * WSZ, kp, vp);

    attn_tc<<<dim3(Sq / 128, Bq * Hn), 256, SMEM_ATT>>>(qh, ql, kp, vp, cp);

    gemm_out<<<dim3(Dm / 128, Mrows / 128), 128, SMEM_GEMM>>>(
        cp, wp + 3 * WSZ, out);
}